// round 4
// baseline (speedup 1.0000x reference)
#include <cuda_runtime.h>

#define ADAPT  32
#define T_LEN  2048
#define NCH    (T_LEN / ADAPT)    // 64 chunks per batch row

// ---------------------------------------------------------------------------
// One block (256 threads) per batch row.
//  Phase A: thread t <-> (step s = t>>3, bin-quad j = t&7). Loads batched
//    4 chunks deep (MLP=4). Packed octet reduction: one pair-exchange SHFL
//    routes p to even / g to odd lanes, then xor-2/xor-4 reduce BOTH sums
//    in a single variable (3 SHFLs total instead of 6).
//  Phase B: per-chunk means, then warp-0 affine scan of the 64-chunk
//    recurrence (S,P) -> (S*mg, P + S*mdot).
//  Phase C: out = P[c] + S[c]*dot, vectorized float4 from smem.
// ---------------------------------------------------------------------------
__global__ void __launch_bounds__(256, 6)
fused_dequant(const float4* __restrict__ x4,
              const float*  __restrict__ qb,
              const float*  __restrict__ cs,
              float*        __restrict__ out)
{
    __shared__ float s_dot[T_LEN];          // 8 KB
    __shared__ float s_g  [T_LEN];          // 8 KB
    __shared__ float s_md[NCH], s_mg[NCH];
    __shared__ float sP[NCH], sS[NCH];

    const int tid  = threadIdx.x;
    const int lane = tid & 31;
    const int w    = tid >> 5;
    const int j    = tid & 7;      // bin quad
    const int srow = tid >> 3;     // step within chunk (0..31)
    const int b    = blockIdx.x;
    const bool odd = (j & 1);

    const float4 b4 = reinterpret_cast<const float4*>(qb)[j];
    const float4 c4 = reinterpret_cast<const float4*>(cs)[j];

    // batch row = 2048*32 floats = 16384 float4; chunk = 256 float4
    const float4* xb = x4 + (size_t)b * 16384;

    // ---- Phase A: 16 iterations x 4 chunks, loads front-batched ----
    for (int cb = 0; cb < NCH; cb += 4) {
        float4 q[4];
#pragma unroll
        for (int u = 0; u < 4; u++) q[u] = xb[(cb + u) * 256 + tid];

#pragma unroll
        for (int u = 0; u < 4; u++) {
            const float p = q[u].x * b4.x + q[u].y * b4.y
                          + q[u].z * b4.z + q[u].w * b4.w;
            const float g = q[u].x * c4.x + q[u].y * c4.y
                          + q[u].z * c4.z + q[u].w * c4.w;
            // pair exchange: even lane collects p-pair-sum, odd collects g
            const float recv = __shfl_xor_sync(0xffffffffu, odd ? p : g, 1);
            float v = (odd ? g : p) + recv;
            v += __shfl_xor_sync(0xffffffffu, v, 2);   // parity-preserving
            v += __shfl_xor_sync(0xffffffffu, v, 4);
            // even lanes now hold total dot over 8 quads, odd lanes total g
            if (j == 0)      s_dot[(cb + u) * 32 + srow] = v;
            else if (j == 1) s_g  [(cb + u) * 32 + srow] = v;
        }
    }
    __syncthreads();

    // ---- Phase B1: per-chunk means (warp w handles chunks 8w..8w+7) ----
#pragma unroll
    for (int i = 0; i < 8; i++) {
        const int c = w * 8 + i;
        float md = s_dot[c * 32 + lane];
        float mg = s_g  [c * 32 + lane];
#pragma unroll
        for (int off = 16; off; off >>= 1) {
            md += __shfl_xor_sync(0xffffffffu, md, off);
            mg += __shfl_xor_sync(0xffffffffu, mg, off);
        }
        if (lane == 0) {
            s_md[c] = md * (1.f / ADAPT);
            s_mg[c] = mg * (1.f / ADAPT);
        }
    }
    __syncthreads();

    // ---- Phase B2: affine scan of 64 chunks in warp 0 (2 chunks/lane) ----
    if (tid < 32) {
        const float md0 = s_md[2 * lane], md1 = s_md[2 * lane + 1];
        const float mg0 = s_mg[2 * lane], mg1 = s_mg[2 * lane + 1];

        float g = mg0 * mg1;            // segment: (S,P)->(S*g, P+S*d)
        float d = md0 + mg0 * md1;
#pragma unroll
        for (int off = 1; off < 32; off <<= 1) {
            const float gp = __shfl_up_sync(0xffffffffu, g, off);
            const float dp = __shfl_up_sync(0xffffffffu, d, off);
            if (lane >= off) { d = dp + gp * d; g = gp * g; }
        }
        float Se = __shfl_up_sync(0xffffffffu, g, 1);
        float Pe = __shfl_up_sync(0xffffffffu, d, 1);
        if (lane == 0) { Se = 1.f; Pe = 0.f; }

        sS[2 * lane]     = Se;
        sP[2 * lane]     = Pe;
        sS[2 * lane + 1] = Se * mg0;
        sP[2 * lane + 1] = Pe + Se * md0;
    }
    __syncthreads();

    // ---- Phase C: vectorized output ----
    const float4* sd4 = reinterpret_cast<const float4*>(s_dot);
    float4* ob4 = reinterpret_cast<float4*>(out + (size_t)b * T_LEN);
#pragma unroll
    for (int k = 0; k < 2; k++) {
        const int u4 = k * 256 + tid;   // float4 index within row (0..511)
        const int c  = u4 >> 3;         // 8 float4 per chunk
        const float P = sP[c];
        const float S = sS[c];
        const float4 q = sd4[u4];
        ob4[u4] = make_float4(P + S * q.x, P + S * q.y,
                              P + S * q.z, P + S * q.w);
    }
}

// ---------------------------------------------------------------------------
extern "C" void kernel_launch(void* const* d_in, const int* in_sizes, int n_in,
                              void* d_out, int out_size)
{
    const float* x  = (const float*)d_in[0];   // (B, T, NB) fp32
    const float* qb = (const float*)d_in[1];   // (NB,)
    const float* cs = (const float*)d_in[2];   // (NB, 1)
    float* out      = (float*)d_out;           // (B, T) fp32

    const int B = out_size / T_LEN;
    fused_dequant<<<B, 256>>>(reinterpret_cast<const float4*>(x), qb, cs, out);
}

// round 5
// speedup vs baseline: 1.0648x; 1.0648x over previous
#include <cuda_runtime.h>

#define ADAPT  32
#define T_LEN  2048
#define NCH    (T_LEN / ADAPT)    // 64 chunks per batch row

// ---------------------------------------------------------------------------
// One block (256 threads) per batch row, 8 blocks/SM.
//  Phase A: thread t <-> (step s = t>>3, bin-quad j = t&7); one coalesced
//    LDG.128 per chunk. Packed 5-shuffle reduce:
//      xor1 routes p->even / g->odd lanes; xor2,xor4 -> per-step octet sums
//      (even lanes: dot[s]; odd lanes: g[s]); xor8,xor16 continue to the
//      warp's 4-step partials of chunk-mean(dot) and chunk-mean(g).
//    Per-step g never materialized; s_g eliminated.
//  Phase B: chunk means from 8 warp-partials each, then warp-0 affine scan
//    of the 64-chunk recurrence (S,P) -> (S*mg, P + S*mdot).
//  Phase C: out = P[c] + S[c]*dot, vectorized float4 from smem.
// ---------------------------------------------------------------------------
__global__ void __launch_bounds__(256, 8)
fused_dequant(const float4* __restrict__ x4,
              const float*  __restrict__ qb,
              const float*  __restrict__ cs,
              float*        __restrict__ out)
{
    __shared__ float s_dot[T_LEN];       // 8 KB  per-step dot
    __shared__ float s_wp [NCH * 8];     // 2 KB  warp partials of p (4 steps)
    __shared__ float s_wg [NCH * 8];     // 2 KB  warp partials of g
    __shared__ float s_md[NCH], s_mg[NCH];
    __shared__ float sP[NCH], sS[NCH];

    const int tid  = threadIdx.x;
    const int lane = tid & 31;
    const int w    = tid >> 5;
    const int j    = tid & 7;            // bin quad
    const int srow = tid >> 3;           // step within chunk (0..31)
    const int b    = blockIdx.x;
    const bool odd = (lane & 1);

    const float4 b4 = reinterpret_cast<const float4*>(qb)[j];
    const float4 c4 = reinterpret_cast<const float4*>(cs)[j];

    // batch row = 2048*32 floats = 16384 float4; chunk = 256 float4
    const float4* xb = x4 + (size_t)b * 16384;

    // ---- Phase A ----
#pragma unroll 2
    for (int c = 0; c < NCH; c++) {
        const float4 q = xb[c * 256 + tid];
        const float p = q.x * b4.x + q.y * b4.y + q.z * b4.z + q.w * b4.w;
        const float g = q.x * c4.x + q.y * c4.y + q.z * c4.z + q.w * c4.w;

        // pair exchange: even lanes collect p, odd lanes collect g
        const float recv = __shfl_xor_sync(0xffffffffu, odd ? p : g, 1);
        float v = (odd ? g : p) + recv;
        v += __shfl_xor_sync(0xffffffffu, v, 2);   // parity-preserving
        v += __shfl_xor_sync(0xffffffffu, v, 4);
        // even lanes: per-step dot over 8 quads; odd lanes: per-step g
        if (j == 0) s_dot[c * 32 + srow] = v;

        // continue to warp partials (sum over this warp's 4 steps)
        float v2 = v + __shfl_xor_sync(0xffffffffu, v, 8);
        v2 += __shfl_xor_sync(0xffffffffu, v2, 16);
        if (lane == 0)      s_wp[c * 8 + w] = v2;   // even: Σ p (4 steps)
        else if (lane == 1) s_wg[c * 8 + w] = v2;   // odd:  Σ g (4 steps)
    }
    __syncthreads();

    // ---- Phase B1: chunk means from 8 warp partials each ----
    if (tid < NCH) {
        const float4* a4 = reinterpret_cast<const float4*>(s_wp + tid * 8);
        const float4 a = a4[0], e = a4[1];
        s_md[tid] = (a.x + a.y + a.z + a.w + e.x + e.y + e.z + e.w)
                    * (1.f / ADAPT);
    } else if (tid < 2 * NCH) {
        const int c = tid - NCH;
        const float4* a4 = reinterpret_cast<const float4*>(s_wg + c * 8);
        const float4 a = a4[0], e = a4[1];
        s_mg[c] = (a.x + a.y + a.z + a.w + e.x + e.y + e.z + e.w)
                  * (1.f / ADAPT);
    }
    __syncthreads();

    // ---- Phase B2: affine scan of 64 chunks in warp 0 (2 chunks/lane) ----
    if (tid < 32) {
        const float md0 = s_md[2 * lane], md1 = s_md[2 * lane + 1];
        const float mg0 = s_mg[2 * lane], mg1 = s_mg[2 * lane + 1];

        float g = mg0 * mg1;             // segment: (S,P)->(S*g, P+S*d)
        float d = md0 + mg0 * md1;
#pragma unroll
        for (int off = 1; off < 32; off <<= 1) {
            const float gp = __shfl_up_sync(0xffffffffu, g, off);
            const float dp = __shfl_up_sync(0xffffffffu, d, off);
            if (lane >= off) { d = dp + gp * d; g = gp * g; }
        }
        float Se = __shfl_up_sync(0xffffffffu, g, 1);
        float Pe = __shfl_up_sync(0xffffffffu, d, 1);
        if (lane == 0) { Se = 1.f; Pe = 0.f; }

        sS[2 * lane]     = Se;
        sP[2 * lane]     = Pe;
        sS[2 * lane + 1] = Se * mg0;
        sP[2 * lane + 1] = Pe + Se * md0;
    }
    __syncthreads();

    // ---- Phase C: vectorized output ----
    const float4* sd4 = reinterpret_cast<const float4*>(s_dot);
    float4* ob4 = reinterpret_cast<float4*>(out + (size_t)b * T_LEN);
#pragma unroll
    for (int k = 0; k < 2; k++) {
        const int u4 = k * 256 + tid;    // float4 index within row (0..511)
        const int c  = u4 >> 3;          // 8 float4 per chunk
        const float P = sP[c];
        const float S = sS[c];
        const float4 q = sd4[u4];
        ob4[u4] = make_float4(P + S * q.x, P + S * q.y,
                              P + S * q.z, P + S * q.w);
    }
}

// ---------------------------------------------------------------------------
extern "C" void kernel_launch(void* const* d_in, const int* in_sizes, int n_in,
                              void* d_out, int out_size)
{
    const float* x  = (const float*)d_in[0];   // (B, T, NB) fp32
    const float* qb = (const float*)d_in[1];   // (NB,)
    const float* cs = (const float*)d_in[2];   // (NB, 1)
    float* out      = (float*)d_out;           // (B, T) fp32

    const int B = out_size / T_LEN;
    fused_dequant<<<B, 256>>>(reinterpret_cast<const float4*>(x), qb, cs, out);
}

// round 6
// speedup vs baseline: 1.2480x; 1.1720x over previous
#include <cuda_runtime.h>

#define ADAPT  32
#define T_LEN  2048
#define NCH    (T_LEN / ADAPT)    // 64 chunks per batch row

// ---------------------------------------------------------------------------
// One block (256 threads) per batch row, 8 blocks/SM (regs must stay <= 32!).
//  Phase A: thread t <-> (step s = t>>3, bin-quad j = t&7). Per chunk:
//    one coalesced streaming LDG.128 (__ldcs), dot vs qb4[j]/cs4[j],
//    two INDEPENDENT 3-step octet shfl chains (p and g, ILP=2)
//    -> s_dot[c*32+s], s_g[c*32+s] in smem.
//  Phase B: per-chunk means (8 warps x 8 chunks), then warp-0 affine scan
//    of the 64-chunk recurrence (S,P) -> (S*mg, P + S*mdot).
//  Phase C: out = P[c] + S[c]*dot, vectorized float4, streaming stores.
// ---------------------------------------------------------------------------
__global__ void __launch_bounds__(256, 8)
fused_dequant(const float4* __restrict__ x4,
              const float*  __restrict__ qb,
              const float*  __restrict__ cs,
              float*        __restrict__ out)
{
    __shared__ float s_dot[T_LEN];          // 8 KB
    __shared__ float s_g  [T_LEN];          // 8 KB
    __shared__ float s_md[NCH], s_mg[NCH];
    __shared__ float sP[NCH], sS[NCH];

    const int tid  = threadIdx.x;
    const int lane = tid & 31;
    const int w    = tid >> 5;
    const int j    = tid & 7;      // bin quad
    const int srow = tid >> 3;     // step within chunk (0..31)
    const int b    = blockIdx.x;

    const float4 b4 = reinterpret_cast<const float4*>(qb)[j];
    const float4 c4 = reinterpret_cast<const float4*>(cs)[j];

    // batch row = 2048*32 floats = 16384 float4; chunk = 256 float4
    const float4* xb = x4 + (size_t)b * 16384;

    // ---- Phase A ----
#pragma unroll 2
    for (int c = 0; c < NCH; c++) {
        const float4 q = __ldcs(&xb[c * 256 + tid]);   // evict-first stream
        float p = q.x * b4.x + q.y * b4.y + q.z * b4.z + q.w * b4.w;
        float g = q.x * c4.x + q.y * c4.y + q.z * c4.z + q.w * c4.w;
        // two independent 3-deep chains (ILP = 2)
        p += __shfl_xor_sync(0xffffffffu, p, 1);
        g += __shfl_xor_sync(0xffffffffu, g, 1);
        p += __shfl_xor_sync(0xffffffffu, p, 2);
        g += __shfl_xor_sync(0xffffffffu, g, 2);
        p += __shfl_xor_sync(0xffffffffu, p, 4);
        g += __shfl_xor_sync(0xffffffffu, g, 4);
        if (j == 0) {
            s_dot[c * 32 + srow] = p;
            s_g  [c * 32 + srow] = g;
        }
    }
    __syncthreads();

    // ---- Phase B1: per-chunk means (warp w handles chunks 8w..8w+7) ----
#pragma unroll
    for (int i = 0; i < 8; i++) {
        const int c = w * 8 + i;
        float md = s_dot[c * 32 + lane];
        float mg = s_g  [c * 32 + lane];
#pragma unroll
        for (int off = 16; off; off >>= 1) {
            md += __shfl_xor_sync(0xffffffffu, md, off);
            mg += __shfl_xor_sync(0xffffffffu, mg, off);
        }
        if (lane == 0) {
            s_md[c] = md * (1.f / ADAPT);
            s_mg[c] = mg * (1.f / ADAPT);
        }
    }
    __syncthreads();

    // ---- Phase B2: affine scan of 64 chunks in warp 0 (2 chunks/lane) ----
    if (tid < 32) {
        const float md0 = s_md[2 * lane], md1 = s_md[2 * lane + 1];
        const float mg0 = s_mg[2 * lane], mg1 = s_mg[2 * lane + 1];

        float g = mg0 * mg1;            // segment: (S,P)->(S*g, P+S*d)
        float d = md0 + mg0 * md1;
#pragma unroll
        for (int off = 1; off < 32; off <<= 1) {
            const float gp = __shfl_up_sync(0xffffffffu, g, off);
            const float dp = __shfl_up_sync(0xffffffffu, d, off);
            if (lane >= off) { d = dp + gp * d; g = gp * g; }
        }
        float Se = __shfl_up_sync(0xffffffffu, g, 1);
        float Pe = __shfl_up_sync(0xffffffffu, d, 1);
        if (lane == 0) { Se = 1.f; Pe = 0.f; }

        sS[2 * lane]     = Se;
        sP[2 * lane]     = Pe;
        sS[2 * lane + 1] = Se * mg0;
        sP[2 * lane + 1] = Pe + Se * md0;
    }
    __syncthreads();

    // ---- Phase C: vectorized output, streaming stores ----
    const float4* sd4 = reinterpret_cast<const float4*>(s_dot);
    float4* ob4 = reinterpret_cast<float4*>(out + (size_t)b * T_LEN);
#pragma unroll
    for (int k = 0; k < 2; k++) {
        const int u4 = k * 256 + tid;   // float4 index within row (0..511)
        const int c  = u4 >> 3;         // 8 float4 per chunk
        const float P = sP[c];
        const float S = sS[c];
        const float4 q = sd4[u4];
        const float4 o = make_float4(P + S * q.x, P + S * q.y,
                                     P + S * q.z, P + S * q.w);
        __stcs(&ob4[u4], o);
    }
}

// ---------------------------------------------------------------------------
extern "C" void kernel_launch(void* const* d_in, const int* in_sizes, int n_in,
                              void* d_out, int out_size)
{
    const float* x  = (const float*)d_in[0];   // (B, T, NB) fp32
    const float* qb = (const float*)d_in[1];   // (NB,)
    const float* cs = (const float*)d_in[2];   // (NB, 1)
    float* out      = (float*)d_out;           // (B, T) fp32

    const int B = out_size / T_LEN;
    fused_dequant<<<B, 256>>>(reinterpret_cast<const float4*>(x), qb, cs, out);
}